// round 3
// baseline (speedup 1.0000x reference)
#include <cuda_runtime.h>
#include <cstdint>

#define IW 320
#define IH 256
#define ND 64
#define NB 2
#define HW (IH*IW)          // 81920
#define DHW (ND*IH*IW)      // 5242880
#define CHW (3*HW)

// [side(2)][batch(2)][12: r00..r22, t0,t1,t2]
__device__ float g_mats[48];

// ---------------- setup: proj = src_proj @ inv(gt_proj) ----------------
__global__ void setup_kernel(const float* __restrict__ lp,
                             const float* __restrict__ rp,
                             const float* __restrict__ gp) {
    if (threadIdx.x != 0 || blockIdx.x != 0) return;
    for (int b = 0; b < NB; ++b) {
        // invert gp[b] (4x4) via Gauss-Jordan in double
        double M[4][8];
        const float* G = gp + 16 * b;
        for (int i = 0; i < 4; i++)
            for (int j = 0; j < 4; j++) {
                M[i][j]     = (double)G[i * 4 + j];
                M[i][j + 4] = (i == j) ? 1.0 : 0.0;
            }
        for (int c = 0; c < 4; c++) {
            int p = c; double best = fabs(M[c][c]);
            for (int r = c + 1; r < 4; r++) {
                double a = fabs(M[r][c]);
                if (a > best) { best = a; p = r; }
            }
            if (p != c)
                for (int j = 0; j < 8; j++) { double t = M[c][j]; M[c][j] = M[p][j]; M[p][j] = t; }
            double inv = 1.0 / M[c][c];
            for (int j = 0; j < 8; j++) M[c][j] *= inv;
            for (int r = 0; r < 4; r++) {
                if (r == c) continue;
                double f = M[r][c];
                for (int j = 0; j < 8; j++) M[r][j] -= f * M[c][j];
            }
        }
        for (int s = 0; s < 2; s++) {
            const float* S = (s == 0 ? lp : rp) + 16 * b;
            float* dst = g_mats + (s * 2 + b) * 12;
            for (int i = 0; i < 3; i++) {
                double row[4];
                for (int j = 0; j < 4; j++) {
                    double acc = 0.0;
                    for (int k = 0; k < 4; k++) acc += (double)S[i * 4 + k] * M[k][j + 4];
                    row[j] = acc;
                }
                dst[i * 3 + 0] = (float)row[0];
                dst[i * 3 + 1] = (float)row[1];
                dst[i * 3 + 2] = (float)row[2];
                dst[9 + i]     = (float)row[3];
            }
        }
    }
}

// ---------------- main kernel ----------------
__device__ __forceinline__ uint32_t rotl32(uint32_t x, int d) {
    return (x << d) | (x >> (32 - d));
}

// JAX partitionable threefry, 32-bit path:
//   counts_hi, counts_lo = iota_2x32_shape(shape)   (hi==0 for our sizes)
//   bits1, bits2 = threefry2x32(k1=0, k2=1, counts_hi, counts_lo)
//   bits = bits1 ^ bits2
__device__ __forceinline__ float tf_uniform(uint32_t lo) {
    uint32_t x0 = 0u;        // counts_hi (=0) + ks0 (=0)
    uint32_t x1 = lo + 1u;   // counts_lo + ks1 (=1)
    const uint32_t ks2 = 0x1BD11BDBu;   // 0x1BD11BDA ^ 0 ^ 1
#define TF_R4(a, b, c, e)                         \
    x0 += x1; x1 = rotl32(x1, a); x1 ^= x0;       \
    x0 += x1; x1 = rotl32(x1, b); x1 ^= x0;       \
    x0 += x1; x1 = rotl32(x1, c); x1 ^= x0;       \
    x0 += x1; x1 = rotl32(x1, e); x1 ^= x0;
    TF_R4(13, 15, 26, 6)   x0 += 1u;   x1 += ks2 + 1u;
    TF_R4(17, 29, 16, 24)  x0 += ks2;  x1 += 2u;
    TF_R4(13, 15, 26, 6)               x1 += 1u + 3u;
    TF_R4(17, 29, 16, 24)  x0 += 1u;   x1 += ks2 + 4u;
    TF_R4(13, 15, 26, 6)   x0 += ks2;  x1 += 5u;
#undef TF_R4
    uint32_t r = x0 ^ x1;
    return __uint_as_float((r >> 9) | 0x3F800000u) - 1.0f;
}

struct BL {
    int   o00, o10, o01, o11;
    float w00, w10, w01, w11;
};

__device__ __forceinline__ BL mkbl(float px, float py) {
    float x0f = floorf(px), y0f = floorf(py);
    float wx = px - x0f, wy = py - y0f;
    float vx0 = (x0f >= 0.f        && x0f <= (float)(IW - 1)) ? 1.f : 0.f;
    float vx1 = (x0f + 1.f >= 0.f  && x0f + 1.f <= (float)(IW - 1)) ? 1.f : 0.f;
    float vy0 = (y0f >= 0.f        && y0f <= (float)(IH - 1)) ? 1.f : 0.f;
    float vy1 = (y0f + 1.f >= 0.f  && y0f + 1.f <= (float)(IH - 1)) ? 1.f : 0.f;
    int xi0 = (int)fminf(fmaxf(x0f,       0.f), (float)(IW - 1));
    int xi1 = (int)fminf(fmaxf(x0f + 1.f, 0.f), (float)(IW - 1));
    int yi0 = (int)fminf(fmaxf(y0f,       0.f), (float)(IH - 1));
    int yi1 = (int)fminf(fmaxf(y0f + 1.f, 0.f), (float)(IH - 1));
    BL b;
    b.o00 = yi0 * IW + xi0; b.o10 = yi0 * IW + xi1;
    b.o01 = yi1 * IW + xi0; b.o11 = yi1 * IW + xi1;
    b.w00 = (1.f - wx) * (1.f - wy) * vx0 * vy0;
    b.w10 = wx * (1.f - wy) * vx1 * vy0;
    b.w01 = (1.f - wx) * wy * vx0 * vy1;
    b.w11 = wx * wy * vx1 * vy1;
    return b;
}

__device__ __forceinline__ float samp(const float* __restrict__ p, const BL& b) {
    return __ldg(p + b.o00) * b.w00 + __ldg(p + b.o10) * b.w10 +
           __ldg(p + b.o01) * b.w01 + __ldg(p + b.o11) * b.w11;
}

__device__ __forceinline__ void project(const float* M, float x, float y, float depth,
                                        float& px, float& py) {
    float rx = M[0] * x + M[1] * y + M[2];
    float ry = M[3] * x + M[4] * y + M[5];
    float rz = M[6] * x + M[7] * y + M[8];
    float zz = rz * depth + M[11];
    bool neg = (zz <= 0.001f);
    float z  = neg ? 1.0f : zz;
    float ax = neg ? (float)IW : (rx * depth + M[9]);
    float ay = neg ? (float)IH : (ry * depth + M[10]);
    px = ax / z;
    py = ay / z;
}

__global__ void __launch_bounds__(256)
volume_kernel(const float* __restrict__ left,
              const float* __restrict__ right,
              float* __restrict__ out) {
    __shared__ float sm[48];
    if (threadIdx.x < 48) sm[threadIdx.x] = g_mats[threadIdx.x];
    __syncthreads();

    int idx = blockIdx.x * blockDim.x + threadIdx.x;
    if (idx >= DHW) return;
    int w  = idx % IW;
    int t1 = idx / IW;
    int h  = t1 % IH;
    int d  = t1 / IH;

    // noise for (b=0, d, h, w) and (b=1, d, h, w): flat indices idx, idx + DHW
    float n0 = tf_uniform((uint32_t)idx);
    float n1 = tf_uniform((uint32_t)(idx + DHW));

    const float inv_max = (float)(1.0 / 40.0);
    const float scale   = (float)(1.0 / 10.0 - 1.0 / 40.0);
    float df = (float)d;
    float s0 = n0 + df, s1 = n1 + df;
    float q0 = inv_max + (s0 * (1.0f / 64.0f)) * scale;
    float q1 = inv_max + (s1 * (1.0f / 64.0f)) * scale;
    float depth0 = __frcp_rn(q0);   // == IEEE 1.0f / q
    float depth1 = __frcp_rn(q1);

    float xs = (float)w, ys = (float)h;

#pragma unroll
    for (int b = 0; b < NB; b++) {
        float depth = b ? depth1 : depth0;
        const float* Lb = left  + b * CHW;
        const float* Rb = right + b * CHW;

        float pxl, pyl, pxr, pyr;
        project(sm + (0 * 2 + b) * 12, xs, ys, depth, pxl, pyl);
        project(sm + (1 * 2 + b) * 12, xs, ys, depth, pxr, pyr);

        BL bl = mkbl(pxl, pyl);
        BL br = mkbl(pxr, pyr);

        float acc = 0.f;
#pragma unroll
        for (int c = 0; c < 3; c++) {
            float lv = samp(Lb + c * HW, bl);
            float rv = samp(Rb + c * HW, br);
            acc += fabsf(rv - lv);
        }
        out[b * DHW + idx] = acc;
    }
}

// ---------------- launch ----------------
extern "C" void kernel_launch(void* const* d_in, const int* in_sizes, int n_in,
                              void* d_out, int out_size) {
    const float* left  = (const float*)d_in[0];
    const float* right = (const float*)d_in[1];
    const float* lp    = (const float*)d_in[2];
    const float* rp    = (const float*)d_in[3];
    const float* gp    = (const float*)d_in[4];

    setup_kernel<<<1, 1>>>(lp, rp, gp);
    volume_kernel<<<DHW / 256, 256>>>(left, right, (float*)d_out);
}

// round 4
// speedup vs baseline: 1.4678x; 1.4678x over previous
#include <cuda_runtime.h>
#include <cstdint>

#define IW 320
#define IH 256
#define ND 64
#define NB 2
#define HW (IH*IW)          // 81920
#define DHW (ND*IH*IW)      // 5242880
#define CHW (3*HW)

// [side(2)][batch(2)][12: r00..r22, t0,t1,t2]
__device__ float g_mats[48];
__device__ int   g_fast;     // 1 => rot==I, t1==t2==0 for all 4 mats

// ---------------- setup: proj = src_proj @ inv(gt_proj) ----------------
__global__ void setup_kernel(const float* __restrict__ lp,
                             const float* __restrict__ rp,
                             const float* __restrict__ gp) {
    if (threadIdx.x != 0 || blockIdx.x != 0) return;
    for (int b = 0; b < NB; ++b) {
        double M[4][8];
        const float* G = gp + 16 * b;
        for (int i = 0; i < 4; i++)
            for (int j = 0; j < 4; j++) {
                M[i][j]     = (double)G[i * 4 + j];
                M[i][j + 4] = (i == j) ? 1.0 : 0.0;
            }
        for (int c = 0; c < 4; c++) {
            int p = c; double best = fabs(M[c][c]);
            for (int r = c + 1; r < 4; r++) {
                double a = fabs(M[r][c]);
                if (a > best) { best = a; p = r; }
            }
            if (p != c)
                for (int j = 0; j < 8; j++) { double t = M[c][j]; M[c][j] = M[p][j]; M[p][j] = t; }
            double inv = 1.0 / M[c][c];
            for (int j = 0; j < 8; j++) M[c][j] *= inv;
            for (int r = 0; r < 4; r++) {
                if (r == c) continue;
                double f = M[r][c];
                for (int j = 0; j < 8; j++) M[r][j] -= f * M[c][j];
            }
        }
        for (int s = 0; s < 2; s++) {
            const float* S = (s == 0 ? lp : rp) + 16 * b;
            float* dst = g_mats + (s * 2 + b) * 12;
            for (int i = 0; i < 3; i++) {
                double row[4];
                for (int j = 0; j < 4; j++) {
                    double acc = 0.0;
                    for (int k = 0; k < 4; k++) acc += (double)S[i * 4 + k] * M[k][j + 4];
                    row[j] = acc;
                }
                dst[i * 3 + 0] = (float)row[0];
                dst[i * 3 + 1] = (float)row[1];
                dst[i * 3 + 2] = (float)row[2];
                dst[9 + i]     = (float)row[3];
            }
        }
    }
    // detect specialized structure: rot == I, t1 == t2 == 0  (t0 free)
    int fast = 1;
    for (int m = 0; m < 4; m++) {
        const float* d = g_mats + m * 12;
        for (int i = 0; i < 3; i++)
            for (int j = 0; j < 3; j++) {
                float want = (i == j) ? 1.0f : 0.0f;
                if (fabsf(d[i * 3 + j] - want) > 1e-4f) fast = 0;
            }
        if (fabsf(d[10]) > 1e-4f || fabsf(d[11]) > 1e-4f) fast = 0;
    }
    g_fast = fast;
}

// ---------------- threefry (JAX partitionable, 32-bit: x0 ^ x1) ----------------
__device__ __forceinline__ uint32_t rotl32(uint32_t x, int d) {
    return __funnelshift_l(x, x, d);
}

__device__ __forceinline__ float tf_uniform(uint32_t lo) {
    uint32_t x0 = 0u;        // counts_hi (=0) + ks0 (=0)
    uint32_t x1 = lo + 1u;   // counts_lo + ks1 (=1)
    const uint32_t ks2 = 0x1BD11BDBu;
#define TF_R4(a, b, c, e)                         \
    x0 += x1; x1 = rotl32(x1, a); x1 ^= x0;       \
    x0 += x1; x1 = rotl32(x1, b); x1 ^= x0;       \
    x0 += x1; x1 = rotl32(x1, c); x1 ^= x0;       \
    x0 += x1; x1 = rotl32(x1, e); x1 ^= x0;
    TF_R4(13, 15, 26, 6)   x0 += 1u;   x1 += ks2 + 1u;
    TF_R4(17, 29, 16, 24)  x0 += ks2;  x1 += 2u;
    TF_R4(13, 15, 26, 6)               x1 += 1u + 3u;
    TF_R4(17, 29, 16, 24)  x0 += 1u;   x1 += ks2 + 4u;
    TF_R4(13, 15, 26, 6)   x0 += ks2;  x1 += 5u;
#undef TF_R4
    uint32_t r = x0 ^ x1;
    return __uint_as_float((r >> 9) | 0x3F800000u) - 1.0f;
}

// ---------------- generic-path helpers ----------------
struct BL {
    int   o00, o10, o01, o11;
    float w00, w10, w01, w11;
};

__device__ __forceinline__ BL mkbl(float px, float py) {
    float x0f = floorf(px), y0f = floorf(py);
    float wx = px - x0f, wy = py - y0f;
    float vx0 = (x0f >= 0.f        && x0f <= (float)(IW - 1)) ? 1.f : 0.f;
    float vx1 = (x0f + 1.f >= 0.f  && x0f + 1.f <= (float)(IW - 1)) ? 1.f : 0.f;
    float vy0 = (y0f >= 0.f        && y0f <= (float)(IH - 1)) ? 1.f : 0.f;
    float vy1 = (y0f + 1.f >= 0.f  && y0f + 1.f <= (float)(IH - 1)) ? 1.f : 0.f;
    int xi0 = (int)fminf(fmaxf(x0f,       0.f), (float)(IW - 1));
    int xi1 = (int)fminf(fmaxf(x0f + 1.f, 0.f), (float)(IW - 1));
    int yi0 = (int)fminf(fmaxf(y0f,       0.f), (float)(IH - 1));
    int yi1 = (int)fminf(fmaxf(y0f + 1.f, 0.f), (float)(IH - 1));
    BL b;
    b.o00 = yi0 * IW + xi0; b.o10 = yi0 * IW + xi1;
    b.o01 = yi1 * IW + xi0; b.o11 = yi1 * IW + xi1;
    b.w00 = (1.f - wx) * (1.f - wy) * vx0 * vy0;
    b.w10 = wx * (1.f - wy) * vx1 * vy0;
    b.w01 = (1.f - wx) * wy * vx0 * vy1;
    b.w11 = wx * wy * vx1 * vy1;
    return b;
}

__device__ __forceinline__ float samp(const float* __restrict__ p, const BL& b) {
    return __ldg(p + b.o00) * b.w00 + __ldg(p + b.o10) * b.w10 +
           __ldg(p + b.o01) * b.w01 + __ldg(p + b.o11) * b.w11;
}

__device__ __forceinline__ void project(const float* M, float x, float y, float depth,
                                        float& px, float& py) {
    float rx = M[0] * x + M[1] * y + M[2];
    float ry = M[3] * x + M[4] * y + M[5];
    float rz = M[6] * x + M[7] * y + M[8];
    float zz = rz * depth + M[11];
    bool neg = (zz <= 0.001f);
    float z  = neg ? 1.0f : zz;
    float ax = neg ? (float)IW : (rx * depth + M[9]);
    float ay = neg ? (float)IH : (ry * depth + M[10]);
    px = ax / z;
    py = ay / z;
}

// ---------------- fast-path helper: 2-tap horizontal ----------------
struct BLX { int o0, o1; float w0, w1; };

__device__ __forceinline__ BLX mkblx(float px) {
    float xf = floorf(px);
    float wx = px - xf;
    float v0 = (xf >= 0.f  && xf <= (float)(IW - 1)) ? 1.f : 0.f;
    float v1 = (xf >= -1.f && xf <= (float)(IW - 2)) ? 1.f : 0.f;
    BLX b;
    b.o0 = (int)fminf(fmaxf(xf,       0.f), (float)(IW - 1));
    b.o1 = (int)fminf(fmaxf(xf + 1.f, 0.f), (float)(IW - 1));
    b.w0 = (1.f - wx) * v0;
    b.w1 = wx * v1;
    return b;
}

__device__ __forceinline__ float samp2(const float* __restrict__ p, const BLX& b) {
    return __ldg(p + b.o0) * b.w0 + __ldg(p + b.o1) * b.w1;
}

// ---------------- main kernel: one block = one image row at one depth ----------------
__global__ void __launch_bounds__(IW)
volume_kernel(const float* __restrict__ left,
              const float* __restrict__ right,
              float* __restrict__ out) {
    __shared__ float sm[48];
    __shared__ int sfast;
    if (threadIdx.x < 48) sm[threadIdx.x] = g_mats[threadIdx.x];
    if (threadIdx.x == 48) sfast = g_fast;
    __syncthreads();

    int w = threadIdx.x;
    int h = blockIdx.x;
    int d = blockIdx.y;
    int idx = (d * IH + h) * IW + w;

    float n0 = tf_uniform((uint32_t)idx);
    float n1 = tf_uniform((uint32_t)(idx + DHW));

    const float inv_max = (float)(1.0 / 40.0);
    const float scale   = (float)(1.0 / 10.0 - 1.0 / 40.0);
    float df = (float)d;
    // q = inverse depth (exactly the reference's pre-reciprocal value)
    float q0 = inv_max + ((n0 + df) * (1.0f / 64.0f)) * scale;
    float q1 = inv_max + ((n1 + df) * (1.0f / 64.0f)) * scale;

    float xs = (float)w;
    int rowoff = h * IW;

    if (sfast) {
        // rot == I, t1 == t2 == 0:  py == y (rows fixed), px = x + t0 * q, no division.
#pragma unroll
        for (int b = 0; b < NB; b++) {
            float q = b ? q1 : q0;
            float t0l = sm[(0 * 2 + b) * 12 + 9];
            float t0r = sm[(1 * 2 + b) * 12 + 9];
            BLX bl = mkblx(fmaf(t0l, q, xs));
            BLX br = mkblx(fmaf(t0r, q, xs));

            const float* Lrow = left  + b * CHW + rowoff;
            const float* Rrow = right + b * CHW + rowoff;
            float acc = 0.f;
#pragma unroll
            for (int c = 0; c < 3; c++) {
                float lv = samp2(Lrow + c * HW, bl);
                float rv = samp2(Rrow + c * HW, br);
                acc += fabsf(rv - lv);
            }
            out[b * DHW + idx] = acc;
        }
    } else {
        float depth0 = __frcp_rn(q0);
        float depth1 = __frcp_rn(q1);
        float ys = (float)h;
#pragma unroll
        for (int b = 0; b < NB; b++) {
            float depth = b ? depth1 : depth0;
            const float* Lb = left  + b * CHW;
            const float* Rb = right + b * CHW;

            float pxl, pyl, pxr, pyr;
            project(sm + (0 * 2 + b) * 12, xs, ys, depth, pxl, pyl);
            project(sm + (1 * 2 + b) * 12, xs, ys, depth, pxr, pyr);

            BL bl = mkbl(pxl, pyl);
            BL br = mkbl(pxr, pyr);

            float acc = 0.f;
#pragma unroll
            for (int c = 0; c < 3; c++) {
                float lv = samp(Lb + c * HW, bl);
                float rv = samp(Rb + c * HW, br);
                acc += fabsf(rv - lv);
            }
            out[b * DHW + idx] = acc;
        }
    }
}

// ---------------- launch ----------------
extern "C" void kernel_launch(void* const* d_in, const int* in_sizes, int n_in,
                              void* d_out, int out_size) {
    const float* left  = (const float*)d_in[0];
    const float* right = (const float*)d_in[1];
    const float* lp    = (const float*)d_in[2];
    const float* rp    = (const float*)d_in[3];
    const float* gp    = (const float*)d_in[4];

    setup_kernel<<<1, 1>>>(lp, rp, gp);
    dim3 grid(IH, ND);
    volume_kernel<<<grid, IW>>>(left, right, (float*)d_out);
}

// round 5
// speedup vs baseline: 1.7739x; 1.2086x over previous
#include <cuda_runtime.h>
#include <cstdint>

#define IW 320
#define IH 256
#define ND 64
#define NB 2
#define HW (IH*IW)          // 81920
#define DHW (ND*IH*IW)      // 5242880
#define CHW (3*HW)

// [side(2)][batch(2)][12: r00..r22, t0,t1,t2]
__device__ float g_mats[48];
__device__ int   g_fast;     // 1 => rot==I, t1==t2==0 for all 4 mats

// ---------------- setup: proj = src_proj @ inv(gt_proj), parallel ----------------
__global__ void setup_kernel(const float* __restrict__ lp,
                             const float* __restrict__ rp,
                             const float* __restrict__ gp) {
    __shared__ double sinv[2][16];
    __shared__ float smats[48];
    int t = threadIdx.x;

    if (t < 2) {
        // cofactor-adjugate 4x4 inverse in double (branch-free, high ILP)
        double m[16];
        const float* G = gp + 16 * t;
#pragma unroll
        for (int i = 0; i < 16; i++) m[i] = (double)G[i];
        double v[16];
        v[0]  =  m[5]*m[10]*m[15] - m[5]*m[11]*m[14] - m[9]*m[6]*m[15] + m[9]*m[7]*m[14] + m[13]*m[6]*m[11] - m[13]*m[7]*m[10];
        v[4]  = -m[4]*m[10]*m[15] + m[4]*m[11]*m[14] + m[8]*m[6]*m[15] - m[8]*m[7]*m[14] - m[12]*m[6]*m[11] + m[12]*m[7]*m[10];
        v[8]  =  m[4]*m[9]*m[15]  - m[4]*m[11]*m[13] - m[8]*m[5]*m[15] + m[8]*m[7]*m[13] + m[12]*m[5]*m[11] - m[12]*m[7]*m[9];
        v[12] = -m[4]*m[9]*m[14]  + m[4]*m[10]*m[13] + m[8]*m[5]*m[14] - m[8]*m[6]*m[13] - m[12]*m[5]*m[10] + m[12]*m[6]*m[9];
        v[1]  = -m[1]*m[10]*m[15] + m[1]*m[11]*m[14] + m[9]*m[2]*m[15] - m[9]*m[3]*m[14] - m[13]*m[2]*m[11] + m[13]*m[3]*m[10];
        v[5]  =  m[0]*m[10]*m[15] - m[0]*m[11]*m[14] - m[8]*m[2]*m[15] + m[8]*m[3]*m[14] + m[12]*m[2]*m[11] - m[12]*m[3]*m[10];
        v[9]  = -m[0]*m[9]*m[15]  + m[0]*m[11]*m[13] + m[8]*m[1]*m[15] - m[8]*m[3]*m[13] - m[12]*m[1]*m[11] + m[12]*m[3]*m[9];
        v[13] =  m[0]*m[9]*m[14]  - m[0]*m[10]*m[13] - m[8]*m[1]*m[14] + m[8]*m[2]*m[13] + m[12]*m[1]*m[10] - m[12]*m[2]*m[9];
        v[2]  =  m[1]*m[6]*m[15]  - m[1]*m[7]*m[14]  - m[5]*m[2]*m[15] + m[5]*m[3]*m[14] + m[13]*m[2]*m[7]  - m[13]*m[3]*m[6];
        v[6]  = -m[0]*m[6]*m[15]  + m[0]*m[7]*m[14]  + m[4]*m[2]*m[15] - m[4]*m[3]*m[14] - m[12]*m[2]*m[7]  + m[12]*m[3]*m[6];
        v[10] =  m[0]*m[5]*m[15]  - m[0]*m[7]*m[13]  - m[4]*m[1]*m[15] + m[4]*m[3]*m[13] + m[12]*m[1]*m[7]  - m[12]*m[3]*m[5];
        v[14] = -m[0]*m[5]*m[14]  + m[0]*m[6]*m[13]  + m[4]*m[1]*m[14] - m[4]*m[2]*m[13] - m[12]*m[1]*m[6]  + m[12]*m[2]*m[5];
        v[3]  = -m[1]*m[6]*m[11]  + m[1]*m[7]*m[10]  + m[5]*m[2]*m[11] - m[5]*m[3]*m[10] - m[9]*m[2]*m[7]   + m[9]*m[3]*m[6];
        v[7]  =  m[0]*m[6]*m[11]  - m[0]*m[7]*m[10]  - m[4]*m[2]*m[11] + m[4]*m[3]*m[10] + m[8]*m[2]*m[7]   - m[8]*m[3]*m[6];
        v[11] = -m[0]*m[5]*m[11]  + m[0]*m[7]*m[9]   + m[4]*m[1]*m[11] - m[4]*m[3]*m[9]  - m[8]*m[1]*m[7]   + m[8]*m[3]*m[5];
        v[15] =  m[0]*m[5]*m[10]  - m[0]*m[6]*m[9]   - m[4]*m[1]*m[10] + m[4]*m[2]*m[9]  + m[8]*m[1]*m[6]   - m[8]*m[2]*m[5];
        double det = m[0]*v[0] + m[1]*v[4] + m[2]*v[8] + m[3]*v[12];
        double rdet = 1.0 / det;
#pragma unroll
        for (int i = 0; i < 16; i++) sinv[t][i] = v[i] * rdet;
    }
    __syncthreads();

    if (t < 48) {
        int mt = t / 12;              // 0..3 = s*2 + b
        int e  = t % 12;              // maps directly to dst offset
        int s  = mt >> 1, b = mt & 1;
        const float* S = (s == 0 ? lp : rp) + 16 * b;
        int i = (e < 9) ? (e / 3) : (e - 9);
        int j = (e < 9) ? (e % 3) : 3;
        double acc = 0.0;
#pragma unroll
        for (int k = 0; k < 4; k++) acc += (double)S[i * 4 + k] * sinv[b][k * 4 + j];
        float f = (float)acc;
        g_mats[mt * 12 + e] = f;
        smats[mt * 12 + e]  = f;
    }
    __syncthreads();

    if (t == 0) {
        int fast = 1;
        for (int mm = 0; mm < 4; mm++) {
            const float* dd = smats + mm * 12;
            for (int i = 0; i < 3; i++)
                for (int j = 0; j < 3; j++) {
                    float want = (i == j) ? 1.0f : 0.0f;
                    if (fabsf(dd[i * 3 + j] - want) > 1e-4f) fast = 0;
                }
            if (fabsf(dd[10]) > 1e-4f || fabsf(dd[11]) > 1e-4f) fast = 0;
        }
        g_fast = fast;
    }
}

// ---------------- threefry (JAX partitionable, 32-bit: x0 ^ x1) ----------------
// rotate-left via mul.wide.u32: {lo,hi} = x * 2^D  =>  lo = x<<D, hi = x>>(32-D).
// (lo | hi) ^ x0 fuses to one LOP3. Puts the rotate on the FMA pipe (IMAD.WIDE)
// instead of SHF on the ALU pipe, balancing the two pipes.
template <int D>
__device__ __forceinline__ uint32_t rotxor(uint32_t x, uint32_t x0) {
    uint32_t lo, hi;
    asm("{\n\t"
        ".reg .u64 t;\n\t"
        "mul.wide.u32 t, %2, %3;\n\t"
        "mov.b64 {%0, %1}, t;\n\t"
        "}"
        : "=r"(lo), "=r"(hi)
        : "r"(x), "r"(1u << D));
    return (lo | hi) ^ x0;
}

__device__ __forceinline__ float tf_uniform(uint32_t lo) {
    uint32_t x0 = 0u;        // counts_hi (=0) + ks0 (=0)
    uint32_t x1 = lo + 1u;   // counts_lo + ks1 (=1)
    const uint32_t ks2 = 0x1BD11BDBu;
#define TF_R(D)  x0 += x1; x1 = rotxor<D>(x1, x0);
#define TF_R4A() TF_R(13) TF_R(15) TF_R(26) TF_R(6)
#define TF_R4B() TF_R(17) TF_R(29) TF_R(16) TF_R(24)
    TF_R4A()  x0 += 1u;   x1 += ks2 + 1u;
    TF_R4B()  x0 += ks2;  x1 += 2u;
    TF_R4A()              x1 += 1u + 3u;
    TF_R4B()  x0 += 1u;   x1 += ks2 + 4u;
    TF_R4A()  x0 += ks2;  x1 += 5u;
#undef TF_R4A
#undef TF_R4B
#undef TF_R
    uint32_t r = x0 ^ x1;
    return __uint_as_float((r >> 9) | 0x3F800000u) - 1.0f;
}

// ---------------- generic-path helpers ----------------
struct BL {
    int   o00, o10, o01, o11;
    float w00, w10, w01, w11;
};

__device__ __forceinline__ BL mkbl(float px, float py) {
    float x0f = floorf(px), y0f = floorf(py);
    float wx = px - x0f, wy = py - y0f;
    float vx0 = (x0f >= 0.f        && x0f <= (float)(IW - 1)) ? 1.f : 0.f;
    float vx1 = (x0f + 1.f >= 0.f  && x0f + 1.f <= (float)(IW - 1)) ? 1.f : 0.f;
    float vy0 = (y0f >= 0.f        && y0f <= (float)(IH - 1)) ? 1.f : 0.f;
    float vy1 = (y0f + 1.f >= 0.f  && y0f + 1.f <= (float)(IH - 1)) ? 1.f : 0.f;
    int xi0 = (int)fminf(fmaxf(x0f,       0.f), (float)(IW - 1));
    int xi1 = (int)fminf(fmaxf(x0f + 1.f, 0.f), (float)(IW - 1));
    int yi0 = (int)fminf(fmaxf(y0f,       0.f), (float)(IH - 1));
    int yi1 = (int)fminf(fmaxf(y0f + 1.f, 0.f), (float)(IH - 1));
    BL b;
    b.o00 = yi0 * IW + xi0; b.o10 = yi0 * IW + xi1;
    b.o01 = yi1 * IW + xi0; b.o11 = yi1 * IW + xi1;
    b.w00 = (1.f - wx) * (1.f - wy) * vx0 * vy0;
    b.w10 = wx * (1.f - wy) * vx1 * vy0;
    b.w01 = (1.f - wx) * wy * vx0 * vy1;
    b.w11 = wx * wy * vx1 * vy1;
    return b;
}

__device__ __forceinline__ float samp(const float* __restrict__ p, const BL& b) {
    return __ldg(p + b.o00) * b.w00 + __ldg(p + b.o10) * b.w10 +
           __ldg(p + b.o01) * b.w01 + __ldg(p + b.o11) * b.w11;
}

__device__ __forceinline__ void project(const float* M, float x, float y, float depth,
                                        float& px, float& py) {
    float rx = __ldg(M+0) * x + __ldg(M+1) * y + __ldg(M+2);
    float ry = __ldg(M+3) * x + __ldg(M+4) * y + __ldg(M+5);
    float rz = __ldg(M+6) * x + __ldg(M+7) * y + __ldg(M+8);
    float zz = rz * depth + __ldg(M+11);
    bool neg = (zz <= 0.001f);
    float z  = neg ? 1.0f : zz;
    float ax = neg ? (float)IW : (rx * depth + __ldg(M+9));
    float ay = neg ? (float)IH : (ry * depth + __ldg(M+10));
    px = ax / z;
    py = ay / z;
}

// ---------------- fast-path helper: 2-tap horizontal ----------------
struct BLX { int o0, o1; float w0, w1; };

__device__ __forceinline__ BLX mkblx(float px) {
    float xf = floorf(px);
    float wx = px - xf;
    float v0 = (xf >= 0.f  && xf <= (float)(IW - 1)) ? 1.f : 0.f;
    float v1 = (xf >= -1.f && xf <= (float)(IW - 2)) ? 1.f : 0.f;
    BLX b;
    b.o0 = (int)fminf(fmaxf(xf,       0.f), (float)(IW - 1));
    b.o1 = (int)fminf(fmaxf(xf + 1.f, 0.f), (float)(IW - 1));
    b.w0 = (1.f - wx) * v0;
    b.w1 = wx * v1;
    return b;
}

__device__ __forceinline__ float samp2(const float* __restrict__ p, const BLX& b) {
    return __ldg(p + b.o0) * b.w0 + __ldg(p + b.o1) * b.w1;
}

// ---------------- main kernel: one block = one image row at one depth ----------------
__global__ void __launch_bounds__(IW)
volume_kernel(const float* __restrict__ left,
              const float* __restrict__ right,
              float* __restrict__ out) {
    int w = threadIdx.x;
    int h = blockIdx.x;
    int d = blockIdx.y;
    int idx = (d * IH + h) * IW + w;

    float n0 = tf_uniform((uint32_t)idx);
    float n1 = tf_uniform((uint32_t)(idx + DHW));

    const float inv_max = (float)(1.0 / 40.0);
    const float scale   = (float)(1.0 / 10.0 - 1.0 / 40.0);
    float df = (float)d;
    // q = inverse depth (exactly the reference's pre-reciprocal value)
    float q0 = inv_max + ((n0 + df) * (1.0f / 64.0f)) * scale;
    float q1 = inv_max + ((n1 + df) * (1.0f / 64.0f)) * scale;

    float xs = (float)w;
    int rowoff = h * IW;

    if (__ldg(&g_fast)) {
        // rot == I, t1 == t2 == 0:  py == y (rows fixed), px = x + t0 * q, no division.
#pragma unroll
        for (int b = 0; b < NB; b++) {
            float q = b ? q1 : q0;
            float t0l = __ldg(&g_mats[(0 * 2 + b) * 12 + 9]);
            float t0r = __ldg(&g_mats[(1 * 2 + b) * 12 + 9]);
            BLX bl = mkblx(fmaf(t0l, q, xs));
            BLX br = mkblx(fmaf(t0r, q, xs));

            const float* Lrow = left  + b * CHW + rowoff;
            const float* Rrow = right + b * CHW + rowoff;
            float acc = 0.f;
#pragma unroll
            for (int c = 0; c < 3; c++) {
                float lv = samp2(Lrow + c * HW, bl);
                float rv = samp2(Rrow + c * HW, br);
                acc += fabsf(rv - lv);
            }
            out[b * DHW + idx] = acc;
        }
    } else {
        float depth0 = __frcp_rn(q0);
        float depth1 = __frcp_rn(q1);
        float ys = (float)h;
#pragma unroll
        for (int b = 0; b < NB; b++) {
            float depth = b ? depth1 : depth0;
            const float* Lb = left  + b * CHW;
            const float* Rb = right + b * CHW;

            float pxl, pyl, pxr, pyr;
            project(g_mats + (0 * 2 + b) * 12, xs, ys, depth, pxl, pyl);
            project(g_mats + (1 * 2 + b) * 12, xs, ys, depth, pxr, pyr);

            BL bl = mkbl(pxl, pyl);
            BL br = mkbl(pxr, pyr);

            float acc = 0.f;
#pragma unroll
            for (int c = 0; c < 3; c++) {
                float lv = samp(Lb + c * HW, bl);
                float rv = samp(Rb + c * HW, br);
                acc += fabsf(rv - lv);
            }
            out[b * DHW + idx] = acc;
        }
    }
}

// ---------------- launch ----------------
extern "C" void kernel_launch(void* const* d_in, const int* in_sizes, int n_in,
                              void* d_out, int out_size) {
    const float* left  = (const float*)d_in[0];
    const float* right = (const float*)d_in[1];
    const float* lp    = (const float*)d_in[2];
    const float* rp    = (const float*)d_in[3];
    const float* gp    = (const float*)d_in[4];

    setup_kernel<<<1, 64>>>(lp, rp, gp);
    dim3 grid(IH, ND);
    volume_kernel<<<grid, IW>>>(left, right, (float*)d_out);
}